// round 1
// baseline (speedup 1.0000x reference)
#include <cuda_runtime.h>

// Problem constants (fixed by reference)
#define NTIME 128
#define NBATCH 1024
#define NSAMP (NTIME*NBATCH)   // 131072
#define NSIZE 8
#define HID 64
#define IN_DIM 10
#define NC 11                  // 1 value col + 10 tangent cols
#define BS 16                  // samples per CTA
#define NCOL (BS*NC)           // 176
#define NT 256                 // threads per CTA

struct SM {
  float w1[HID*HID];      // w_int[0] transposed: [k][i]
  float w2[HID*HID];      // w_int[1] transposed: [k][i]
  float ws[HID*IN_DIM];   // w_start row-major [i][j]
  float we[NSIZE*HID];    // w_end row-major [r][k]
  float bs[HID];
  float b1[HID];
  float b2[HID];
  float be[NSIZE];
  float inp[BS][IN_DIM];  // per-sample x = [y(8), erate, T]
  float sc[BS][5];        // per-sample epilogue scalars
  float A[HID*NCOL];      // state matrix buffer
  float Bb[HID*NCOL];     // state matrix buffer
};

// One hidden layer: Y[64 x NCOL] = mask(W @ X + b), tangent cols masked.
// Thread (ty,tx): rows r0..r0+3, the 11 columns of sample tx.
__device__ __forceinline__ void layer64(const float* __restrict__ W,
                                        const float* __restrict__ bias,
                                        const float* __restrict__ X,
                                        float* __restrict__ Y,
                                        int r0, int c0)
{
  float acc[4][NC];
  #pragma unroll
  for (int r = 0; r < 4; r++)
    #pragma unroll
    for (int j = 0; j < NC; j++) acc[r][j] = 0.f;

  #pragma unroll 8
  for (int k = 0; k < HID; k++) {
    float4 w = *reinterpret_cast<const float4*>(W + k*HID + r0);
    float xv[NC];
    #pragma unroll
    for (int j = 0; j < NC; j++) xv[j] = X[k*NCOL + c0 + j];
    #pragma unroll
    for (int j = 0; j < NC; j++) {
      acc[0][j] = fmaf(w.x, xv[j], acc[0][j]);
      acc[1][j] = fmaf(w.y, xv[j], acc[1][j]);
      acc[2][j] = fmaf(w.z, xv[j], acc[2][j]);
      acc[3][j] = fmaf(w.w, xv[j], acc[3][j]);
    }
  }
  #pragma unroll
  for (int r = 0; r < 4; r++) {
    float pre = acc[r][0] + bias[r0 + r];
    float m = pre > 0.f ? 1.f : 0.f;
    float* yr = Y + (r0 + r)*NCOL + c0;
    yr[0] = pre > 0.f ? pre : 0.f;
    #pragma unroll
    for (int j = 1; j < NC; j++) yr[j] = m * acc[r][j];
  }
}

__global__ __launch_bounds__(NT) void model_kernel(
    const float* __restrict__ y, const float* __restrict__ erate,
    const float* __restrict__ Tp, const float* __restrict__ Ep,
    const float* __restrict__ np_, const float* __restrict__ w_start,
    const float* __restrict__ b_start, const float* __restrict__ w_int,
    const float* __restrict__ b_int, const float* __restrict__ w_end,
    const float* __restrict__ b_end, float* __restrict__ out)
{
  extern __shared__ char smraw[];
  SM& s = *reinterpret_cast<SM*>(smraw);
  const int tid = threadIdx.x;
  const int samp0 = blockIdx.x * BS;

  // ---- load weights (transpose hidden weights to [k][i]) ----
  for (int idx = tid; idx < HID*HID; idx += NT) {
    int i = idx / HID, k = idx % HID;
    s.w1[k*HID + i] = w_int[idx];
    s.w2[k*HID + i] = w_int[HID*HID + idx];
  }
  for (int idx = tid; idx < HID*IN_DIM; idx += NT) s.ws[idx] = w_start[idx];
  for (int idx = tid; idx < NSIZE*HID; idx += NT) s.we[idx] = w_end[idx];
  if (tid < HID) { s.bs[tid] = b_start[tid]; s.b1[tid] = b_int[tid]; s.b2[tid] = b_int[HID + tid]; }
  else if (tid < HID + NSIZE) s.be[tid - HID] = b_end[tid - HID];

  // ---- load per-sample inputs ----
  for (int idx = tid; idx < BS*IN_DIM; idx += NT) {
    int sm = idx / IN_DIM, j = idx % IN_DIM;
    int g = samp0 + sm;
    float v = (j < NSIZE) ? y[g*NSIZE + j] : ((j == NSIZE) ? erate[g] : Tp[g]);
    s.inp[sm][j] = v;
  }
  __syncthreads();

  const int tx = tid & (BS - 1);   // sample within CTA
  const int ty = tid >> 4;         // 0..15 -> 4-row tile
  const int r0 = ty * 4;
  const int c0 = tx * NC;

  // ---- start layer: col0 = relu(Ws x + b); tangent col j = mask * Ws[:,j] ----
  {
    float xin[IN_DIM];
    #pragma unroll
    for (int j = 0; j < IN_DIM; j++) xin[j] = s.inp[tx][j];
    #pragma unroll
    for (int r = 0; r < 4; r++) {
      int i = r0 + r;
      float pre = s.bs[i];
      #pragma unroll
      for (int j = 0; j < IN_DIM; j++) pre = fmaf(s.ws[i*IN_DIM + j], xin[j], pre);
      float m = pre > 0.f ? 1.f : 0.f;
      float* ar = s.A + i*NCOL + c0;
      ar[0] = pre > 0.f ? pre : 0.f;
      #pragma unroll
      for (int j = 0; j < IN_DIM; j++) ar[1 + j] = m * s.ws[i*IN_DIM + j];
    }
  }
  __syncthreads();

  layer64(s.w1, s.b1, s.A, s.Bb, r0, c0);
  __syncthreads();
  layer64(s.w2, s.b2, s.Bb, s.A, r0, c0);
  __syncthreads();

  // ---- end layer: S[8 x NCOL] = We @ X (+ b_end on value cols) into Bb rows 0..7 ----
  for (int idx = tid; idx < NSIZE*NCOL; idx += NT) {
    int r = idx / NCOL, c = idx - r*NCOL;
    float acc = 0.f;
    const float* wr = s.we + r*HID;
    #pragma unroll 8
    for (int k = 0; k < HID; k++) acc = fmaf(wr[k], s.A[k*NCOL + c], acc);
    s.Bb[r*NCOL + c] = acc + ((c % NC) == 0 ? s.be[r] : 0.f);
  }
  __syncthreads();

  // ---- per-sample epilogue scalars ----
  if (tid < BS) {
    int sm = tid;
    int cc = sm * NC;
    float st0 = s.Bb[cc];                 // state[0] (row 0, value col)
    float y0  = s.inp[sm][0];
    float sg  = (y0 > 0.f) ? 1.f : ((y0 < 0.f) ? -1.f : 0.f);
    float a   = fabsf(y0);
    float p   = expf(np_[0]);
    float Ee  = expf(Ep[0]);
    float onep = 1.f + st0 * 1e-5f;
    float u   = a * onep;
    float g   = (u > 0.f) ? powf(u, p) : 0.f;  // macaulay(g)=g since g>=0
    float dgdu = (u > 0.f) ? p * g / u : 0.f;
    float coef = -Ee * sg * dgdu;
    float er  = s.inp[sm][NSIZE];
    s.sc[sm][0] = sg * onep;              // d u / d y0 (direct part)
    s.sc[sm][1] = a * 1e-5f;              // d u / d s0
    s.sc[sm][2] = coef;
    s.sc[sm][3] = Ee * (er - g * sg);     // flow value
    s.sc[sm][4] = Ee;
  }
  __syncthreads();

  // ---- write outputs: one thread per (sample, output row) ----
  if (tid < BS*NSIZE) {
    int sm = tid >> 3;
    int r  = tid & 7;
    int cc = sm * NC;
    int g  = samp0 + sm;
    float S[NC];
    #pragma unroll
    for (int j = 0; j < NC; j++) S[j] = s.Bb[r*NCOL + cc + j];
    float son  = s.sc[sm][0], a5 = s.sc[sm][1], coef = s.sc[sm][2];
    float flow = s.sc[sm][3], Ee = s.sc[sm][4];

    float rate, j1[8], j2v, j3v;
    if (r == 0) {
      rate = flow;
      #pragma unroll
      for (int j = 0; j < 8; j++) {
        float du = a5 * S[1 + j] + (j == 0 ? son : 0.f);
        j1[j] = coef * du;
      }
      j2v = Ee + coef * (a5 * S[9]);   // direct erate term + via s0
      j3v = coef * (a5 * S[10]);
    } else {
      rate = S[0] * 1e-4f;
      #pragma unroll
      for (int j = 0; j < 8; j++) j1[j] = S[1 + j] * 1e-4f;
      j2v = S[9]  * 1e-4f;
      j3v = S[10] * 1e-4f;
    }

    out[(size_t)g*NSIZE + r] = rate;
    const size_t b1o = (size_t)NSAMP * NSIZE;
    float* o1 = out + b1o + (size_t)g*64 + (size_t)r*8;
    #pragma unroll
    for (int j = 0; j < 8; j++) o1[j] = j1[j];
    const size_t b2o = b1o + (size_t)NSAMP * 64;
    out[b2o + (size_t)g*NSIZE + r] = j2v;
    out[b2o + (size_t)NSAMP*NSIZE + (size_t)g*NSIZE + r] = j3v;
  }
}

extern "C" void kernel_launch(void* const* d_in, const int* in_sizes, int n_in,
                              void* d_out, int out_size)
{
  const float* y       = (const float*)d_in[1];
  const float* erate   = (const float*)d_in[2];
  const float* T       = (const float*)d_in[3];
  const float* E       = (const float*)d_in[4];
  const float* n       = (const float*)d_in[5];
  const float* w_start = (const float*)d_in[6];
  const float* b_start = (const float*)d_in[7];
  const float* w_int   = (const float*)d_in[8];
  const float* b_int   = (const float*)d_in[9];
  const float* w_end   = (const float*)d_in[10];
  const float* b_end   = (const float*)d_in[11];
  float* out = (float*)d_out;

  int shbytes = (int)sizeof(SM);
  cudaFuncSetAttribute(model_kernel, cudaFuncAttributeMaxDynamicSharedMemorySize, shbytes);
  model_kernel<<<NSAMP/BS, NT, shbytes>>>(y, erate, T, E, n, w_start, b_start,
                                          w_int, b_int, w_end, b_end, out);
}

// round 2
// speedup vs baseline: 1.1382x; 1.1382x over previous
#include <cuda_runtime.h>

// Problem constants (fixed by reference)
#define NTIME 128
#define NBATCH 1024
#define NSAMP (NTIME*NBATCH)   // 131072
#define NSIZE 8
#define HID 64
#define IN_DIM 10
#define NC 12                  // 1 value col + 10 tangent cols + 1 zero pad
#define BS 16                  // samples per CTA
#define NCOL (BS*NC)           // 192
#define NT 256                 // threads per CTA

typedef unsigned long long u64;

struct SM {
  float w1[HID*HID];      // w_int[0] transposed: [k][i]
  float w2[HID*HID];      // w_int[1] transposed: [k][i]
  float ws[HID*IN_DIM];   // w_start row-major [i][j]
  float we[NSIZE*HID];    // w_end row-major [r][k]
  float bs[HID];
  float b1[HID];
  float b2[HID];
  float be[NSIZE];
  float inp[BS][IN_DIM];  // per-sample x = [y(8), erate, T]
  float sc[BS][5];        // per-sample epilogue scalars
  float A[HID*NCOL];      // state matrix buffer
  float Bb[HID*NCOL];     // state matrix buffer
};

__device__ __forceinline__ u64 pack2(float a, float b) {
  u64 r; asm("mov.b64 %0, {%1, %2};" : "=l"(r) : "f"(a), "f"(b)); return r;
}
__device__ __forceinline__ void unpack2(u64 v, float& a, float& b) {
  asm("mov.b64 {%0, %1}, %2;" : "=f"(a), "=f"(b) : "l"(v));
}
__device__ __forceinline__ void fma2(u64& d, u64 a, u64 b) {
  asm("fma.rn.f32x2 %0, %1, %2, %3;" : "=l"(d) : "l"(a), "l"(b), "l"(d));
}

// One hidden layer: Y[64 x NCOL] = mask(W @ X + b), tangent cols masked.
// Thread (ty,tx): rows r0..r0+3, the 12 padded columns of sample tx.
__device__ __forceinline__ void layer64(const float* __restrict__ W,
                                        const float* __restrict__ bias,
                                        const float* __restrict__ X,
                                        float* __restrict__ Y,
                                        int r0, int c0)
{
  u64 acc[4][6];
  #pragma unroll
  for (int r = 0; r < 4; r++)
    #pragma unroll
    for (int p = 0; p < 6; p++) acc[r][p] = 0ull;

  const float* Xb = X + c0;
  const float* Wb = W + r0;

  #pragma unroll 4
  for (int k = 0; k < HID; k++) {
    float4 w = *reinterpret_cast<const float4*>(Wb + k*HID);
    u64 wp[4];
    wp[0] = pack2(w.x, w.x); wp[1] = pack2(w.y, w.y);
    wp[2] = pack2(w.z, w.z); wp[3] = pack2(w.w, w.w);

    const ulonglong2* xp = reinterpret_cast<const ulonglong2*>(Xb + k*NCOL);
    ulonglong2 xa = xp[0], xb = xp[1], xc = xp[2];
    u64 xv[6] = { xa.x, xa.y, xb.x, xb.y, xc.x, xc.y };

    #pragma unroll
    for (int r = 0; r < 4; r++)
      #pragma unroll
      for (int p = 0; p < 6; p++)
        fma2(acc[r][p], wp[r], xv[p]);
  }

  #pragma unroll
  for (int r = 0; r < 4; r++) {
    float v[12];
    #pragma unroll
    for (int p = 0; p < 6; p++) unpack2(acc[r][p], v[2*p], v[2*p+1]);
    float pre = v[0] + bias[r0 + r];
    float m = pre > 0.f ? 1.f : 0.f;
    v[0] = pre > 0.f ? pre : 0.f;
    #pragma unroll
    for (int j = 1; j < 12; j++) v[j] *= m;
    float4* yr = reinterpret_cast<float4*>(Y + (r0 + r)*NCOL + c0);
    yr[0] = make_float4(v[0], v[1], v[2],  v[3]);
    yr[1] = make_float4(v[4], v[5], v[6],  v[7]);
    yr[2] = make_float4(v[8], v[9], v[10], v[11]);
  }
}

__global__ __launch_bounds__(NT) void model_kernel(
    const float* __restrict__ y, const float* __restrict__ erate,
    const float* __restrict__ Tp, const float* __restrict__ Ep,
    const float* __restrict__ np_, const float* __restrict__ w_start,
    const float* __restrict__ b_start, const float* __restrict__ w_int,
    const float* __restrict__ b_int, const float* __restrict__ w_end,
    const float* __restrict__ b_end, float* __restrict__ out)
{
  extern __shared__ char smraw[];
  SM& s = *reinterpret_cast<SM*>(smraw);
  const int tid = threadIdx.x;
  const int samp0 = blockIdx.x * BS;

  // ---- load weights (transpose hidden weights to [k][i]) ----
  for (int idx = tid; idx < HID*HID; idx += NT) {
    int i = idx / HID, k = idx % HID;
    s.w1[k*HID + i] = w_int[idx];
    s.w2[k*HID + i] = w_int[HID*HID + idx];
  }
  for (int idx = tid; idx < HID*IN_DIM; idx += NT) s.ws[idx] = w_start[idx];
  for (int idx = tid; idx < NSIZE*HID; idx += NT) s.we[idx] = w_end[idx];
  if (tid < HID) { s.bs[tid] = b_start[tid]; s.b1[tid] = b_int[tid]; s.b2[tid] = b_int[HID + tid]; }
  else if (tid < HID + NSIZE) s.be[tid - HID] = b_end[tid - HID];

  // ---- load per-sample inputs ----
  for (int idx = tid; idx < BS*IN_DIM; idx += NT) {
    int sm = idx / IN_DIM, j = idx % IN_DIM;
    int g = samp0 + sm;
    float v = (j < NSIZE) ? y[g*NSIZE + j] : ((j == NSIZE) ? erate[g] : Tp[g]);
    s.inp[sm][j] = v;
  }
  __syncthreads();

  const int tx = tid & (BS - 1);   // sample within CTA
  const int ty = tid >> 4;         // 0..15 -> 4-row tile
  const int r0 = ty * 4;
  const int c0 = tx * NC;

  // ---- start layer: col0 = relu(Ws x + b); tangent col j = mask * Ws[:,j]; pad=0 ----
  {
    float xin[IN_DIM];
    #pragma unroll
    for (int j = 0; j < IN_DIM; j++) xin[j] = s.inp[tx][j];
    #pragma unroll
    for (int r = 0; r < 4; r++) {
      int i = r0 + r;
      float pre = s.bs[i];
      #pragma unroll
      for (int j = 0; j < IN_DIM; j++) pre = fmaf(s.ws[i*IN_DIM + j], xin[j], pre);
      float m = pre > 0.f ? 1.f : 0.f;
      float* ar = s.A + i*NCOL + c0;
      ar[0] = pre > 0.f ? pre : 0.f;
      #pragma unroll
      for (int j = 0; j < IN_DIM; j++) ar[1 + j] = m * s.ws[i*IN_DIM + j];
      ar[11] = 0.f;
    }
  }
  __syncthreads();

  layer64(s.w1, s.b1, s.A, s.Bb, r0, c0);
  __syncthreads();
  layer64(s.w2, s.b2, s.Bb, s.A, r0, c0);
  __syncthreads();

  // ---- end layer: S[8 x NCOL] = We @ X (+ b_end on value cols), f32x2 over col pairs ----
  // 8 rows x 96 col-pairs = 768 pair-slots; 256 threads -> 3 each.
  for (int idx = tid; idx < NSIZE*(NCOL/2); idx += NT) {
    int r = idx / (NCOL/2), pc = idx - r*(NCOL/2);
    int c = 2*pc;
    u64 acc = 0ull;
    const float* wr = s.we + r*HID;
    const float* xb = s.A + c;
    #pragma unroll 8
    for (int k = 0; k < HID; k++) {
      float w = wr[k];
      u64 xv = *reinterpret_cast<const u64*>(xb + k*NCOL);
      fma2(acc, pack2(w, w), xv);
    }
    float lo, hi; unpack2(acc, lo, hi);
    if ((c % NC) == 0) lo += s.be[r];
    float2 res = make_float2(lo, hi);
    *reinterpret_cast<float2*>(s.Bb + r*NCOL + c) = res;
  }
  __syncthreads();

  // ---- per-sample epilogue scalars ----
  if (tid < BS) {
    int sm = tid;
    int cc = sm * NC;
    float st0 = s.Bb[cc];                 // state[0] (row 0, value col)
    float y0  = s.inp[sm][0];
    float sg  = (y0 > 0.f) ? 1.f : ((y0 < 0.f) ? -1.f : 0.f);
    float a   = fabsf(y0);
    float p   = expf(np_[0]);
    float Ee  = expf(Ep[0]);
    float onep = 1.f + st0 * 1e-5f;
    float u   = a * onep;
    float g   = (u > 0.f) ? powf(u, p) : 0.f;  // macaulay(g)=g since g>=0
    float dgdu = (u > 0.f) ? p * g / u : 0.f;
    float coef = -Ee * sg * dgdu;
    float er  = s.inp[sm][NSIZE];
    s.sc[sm][0] = sg * onep;              // d u / d y0 (direct part)
    s.sc[sm][1] = a * 1e-5f;              // d u / d s0
    s.sc[sm][2] = coef;
    s.sc[sm][3] = Ee * (er - g * sg);     // flow value
    s.sc[sm][4] = Ee;
  }
  __syncthreads();

  // ---- write outputs: one thread per (sample, output row) ----
  if (tid < BS*NSIZE) {
    int sm = tid >> 3;
    int r  = tid & 7;
    int cc = sm * NC;
    int g  = samp0 + sm;
    float S[11];
    #pragma unroll
    for (int j = 0; j < 11; j++) S[j] = s.Bb[r*NCOL + cc + j];
    float son  = s.sc[sm][0], a5 = s.sc[sm][1], coef = s.sc[sm][2];
    float flow = s.sc[sm][3], Ee = s.sc[sm][4];

    float rate, j1[8], j2v, j3v;
    if (r == 0) {
      rate = flow;
      #pragma unroll
      for (int j = 0; j < 8; j++) {
        float du = a5 * S[1 + j] + (j == 0 ? son : 0.f);
        j1[j] = coef * du;
      }
      j2v = Ee + coef * (a5 * S[9]);   // direct erate term + via s0
      j3v = coef * (a5 * S[10]);
    } else {
      rate = S[0] * 1e-4f;
      #pragma unroll
      for (int j = 0; j < 8; j++) j1[j] = S[1 + j] * 1e-4f;
      j2v = S[9]  * 1e-4f;
      j3v = S[10] * 1e-4f;
    }

    out[(size_t)g*NSIZE + r] = rate;
    const size_t b1o = (size_t)NSAMP * NSIZE;
    float* o1 = out + b1o + (size_t)g*64 + (size_t)r*8;
    #pragma unroll
    for (int j = 0; j < 8; j++) o1[j] = j1[j];
    const size_t b2o = b1o + (size_t)NSAMP * 64;
    out[b2o + (size_t)g*NSIZE + r] = j2v;
    out[b2o + (size_t)NSAMP*NSIZE + (size_t)g*NSIZE + r] = j3v;
  }
}

extern "C" void kernel_launch(void* const* d_in, const int* in_sizes, int n_in,
                              void* d_out, int out_size)
{
  const float* y       = (const float*)d_in[1];
  const float* erate   = (const float*)d_in[2];
  const float* T       = (const float*)d_in[3];
  const float* E       = (const float*)d_in[4];
  const float* n       = (const float*)d_in[5];
  const float* w_start = (const float*)d_in[6];
  const float* b_start = (const float*)d_in[7];
  const float* w_int   = (const float*)d_in[8];
  const float* b_int   = (const float*)d_in[9];
  const float* w_end   = (const float*)d_in[10];
  const float* b_end   = (const float*)d_in[11];
  float* out = (float*)d_out;

  int shbytes = (int)sizeof(SM);
  cudaFuncSetAttribute(model_kernel, cudaFuncAttributeMaxDynamicSharedMemorySize, shbytes);
  model_kernel<<<NSAMP/BS, NT, shbytes>>>(y, erate, T, E, n, w_start, b_start,
                                          w_int, b_int, w_end, b_end, out);
}

// round 3
// speedup vs baseline: 1.4891x; 1.3083x over previous
#include <cuda_runtime.h>

// Problem constants (fixed by reference)
#define NTIME 128
#define NBATCH 1024
#define NSAMP (NTIME*NBATCH)   // 131072
#define NSIZE 8
#define HID 64
#define IN_DIM 10
#define NC 12                  // 1 value col + 10 tangent cols + 1 zero pad
#define BS 24                  // samples per tile
#define NCOL (BS*NC)           // 288
#define NT 384                 // threads per CTA
#define NTILES ((NSAMP + BS - 1) / BS)   // 5462
#define GRID 148

typedef unsigned long long u64;

struct SM {
  float A[HID*NCOL];        // 73728 B
  float Bb[HID*NCOL];       // 73728 B
  float w1d[HID*2*HID];     // w_int[0] transposed+duplicated: [k][2i],[2i+1]
  float w2d[HID*2*HID];     // w_int[1] same
  float wed[NSIZE*2*HID];   // w_end duplicated: [r][2k],[2k+1]
  float ws[HID*IN_DIM];     // w_start row-major
  float bs[HID];
  float b1[HID];
  float b2[HID];
  float be[NSIZE];
  float inp[BS][IN_DIM];
  float sc[BS][5];
  float pconst, Econst;
};

__device__ __forceinline__ u64 pack2(float a, float b) {
  u64 r; asm("mov.b64 %0, {%1, %2};" : "=l"(r) : "f"(a), "f"(b)); return r;
}
__device__ __forceinline__ void unpack2(u64 v, float& a, float& b) {
  asm("mov.b64 {%0, %1}, %2;" : "=f"(a), "=f"(b) : "l"(v));
}
__device__ __forceinline__ void fma2(u64& d, u64 a, u64 b) {
  asm("fma.rn.f32x2 %0, %1, %2, %3;" : "=l"(d) : "l"(a), "l"(b), "l"(d));
}

// One hidden layer: Y[64 x NCOL] = mask(W @ X + b), tangent cols masked.
// Thread (ty,tx): rows r0..r0+3, the 12 padded columns of sample tx.
// Wd holds duplicated pairs: Wd[k*128 + 2i] = Wd[k*128 + 2i + 1] = W[i][k].
__device__ __forceinline__ void layer64(const float* __restrict__ Wd,
                                        const float* __restrict__ bias,
                                        const float* __restrict__ X,
                                        float* __restrict__ Y,
                                        int r0, int c0)
{
  u64 acc[4][6];
  #pragma unroll
  for (int r = 0; r < 4; r++)
    #pragma unroll
    for (int p = 0; p < 6; p++) acc[r][p] = 0ull;

  const float* Xb = X + c0;
  const float* Wb = Wd + 2*r0;

  #pragma unroll 4
  for (int k = 0; k < HID; k++) {
    const ulonglong2* wq = reinterpret_cast<const ulonglong2*>(Wb + k*2*HID);
    ulonglong2 wa = wq[0], wb = wq[1];
    u64 wp[4] = { wa.x, wa.y, wb.x, wb.y };

    const ulonglong2* xp = reinterpret_cast<const ulonglong2*>(Xb + k*NCOL);
    ulonglong2 xa = xp[0], xb2 = xp[1], xc = xp[2];
    u64 xv[6] = { xa.x, xa.y, xb2.x, xb2.y, xc.x, xc.y };

    #pragma unroll
    for (int r = 0; r < 4; r++)
      #pragma unroll
      for (int p = 0; p < 6; p++)
        fma2(acc[r][p], wp[r], xv[p]);
  }

  #pragma unroll
  for (int r = 0; r < 4; r++) {
    float v[12];
    #pragma unroll
    for (int p = 0; p < 6; p++) unpack2(acc[r][p], v[2*p], v[2*p+1]);
    float pre = v[0] + bias[r0 + r];
    float m = pre > 0.f ? 1.f : 0.f;
    v[0] = pre > 0.f ? pre : 0.f;
    #pragma unroll
    for (int j = 1; j < 12; j++) v[j] *= m;
    float4* yr = reinterpret_cast<float4*>(Y + (r0 + r)*NCOL + c0);
    yr[0] = make_float4(v[0], v[1], v[2],  v[3]);
    yr[1] = make_float4(v[4], v[5], v[6],  v[7]);
    yr[2] = make_float4(v[8], v[9], v[10], v[11]);
  }
}

__global__ __launch_bounds__(NT) void model_kernel(
    const float* __restrict__ y, const float* __restrict__ erate,
    const float* __restrict__ Tp, const float* __restrict__ Ep,
    const float* __restrict__ np_, const float* __restrict__ w_start,
    const float* __restrict__ b_start, const float* __restrict__ w_int,
    const float* __restrict__ b_int, const float* __restrict__ w_end,
    const float* __restrict__ b_end, float* __restrict__ out)
{
  extern __shared__ char smraw[];
  SM& s = *reinterpret_cast<SM*>(smraw);
  const int tid = threadIdx.x;

  // ---- one-time weight load: transpose + duplicate for f32x2 ----
  for (int idx = tid; idx < HID*HID; idx += NT) {
    int i = idx / HID, k = idx % HID;
    float v1 = w_int[idx], v2 = w_int[HID*HID + idx];
    s.w1d[k*2*HID + 2*i]     = v1;
    s.w1d[k*2*HID + 2*i + 1] = v1;
    s.w2d[k*2*HID + 2*i]     = v2;
    s.w2d[k*2*HID + 2*i + 1] = v2;
  }
  for (int idx = tid; idx < NSIZE*HID; idx += NT) {
    int r = idx / HID, k = idx % HID;
    float v = w_end[idx];
    s.wed[r*2*HID + 2*k]     = v;
    s.wed[r*2*HID + 2*k + 1] = v;
  }
  for (int idx = tid; idx < HID*IN_DIM; idx += NT) s.ws[idx] = w_start[idx];
  if (tid < HID) { s.bs[tid] = b_start[tid]; s.b1[tid] = b_int[tid]; s.b2[tid] = b_int[HID + tid]; }
  else if (tid < HID + NSIZE) s.be[tid - HID] = b_end[tid - HID];
  else if (tid == HID + NSIZE) { s.pconst = expf(np_[0]); s.Econst = expf(Ep[0]); }

  const int tx = tid % BS;     // sample within tile
  const int ty = tid / BS;     // 0..15 -> 4-row tile
  const int r0 = ty * 4;
  const int c0 = tx * NC;

  for (int tile = blockIdx.x; tile < NTILES; tile += GRID) {
    const int samp0 = tile * BS;

    // ---- load per-sample inputs (guarded for tail tile) ----
    if (tid < BS*IN_DIM) {
      int sm = tid / IN_DIM, j = tid % IN_DIM;
      int g = samp0 + sm;
      float v = 0.f;
      if (g < NSAMP)
        v = (j < NSIZE) ? y[(size_t)g*NSIZE + j] : ((j == NSIZE) ? erate[g] : Tp[g]);
      s.inp[sm][j] = v;
    }
    __syncthreads();

    // ---- start layer: col0 = relu(Ws x + b); tangent col j = mask*Ws[:,j]; pad=0 ----
    {
      float xin[IN_DIM];
      #pragma unroll
      for (int j = 0; j < IN_DIM; j++) xin[j] = s.inp[tx][j];
      #pragma unroll
      for (int r = 0; r < 4; r++) {
        int i = r0 + r;
        float wrow[IN_DIM];
        #pragma unroll
        for (int j = 0; j < IN_DIM; j++) wrow[j] = s.ws[i*IN_DIM + j];
        float pre = s.bs[i];
        #pragma unroll
        for (int j = 0; j < IN_DIM; j++) pre = fmaf(wrow[j], xin[j], pre);
        float m = pre > 0.f ? 1.f : 0.f;
        float v0 = pre > 0.f ? pre : 0.f;
        float4* ar = reinterpret_cast<float4*>(s.A + i*NCOL + c0);
        ar[0] = make_float4(v0, m*wrow[0], m*wrow[1], m*wrow[2]);
        ar[1] = make_float4(m*wrow[3], m*wrow[4], m*wrow[5], m*wrow[6]);
        ar[2] = make_float4(m*wrow[7], m*wrow[8], m*wrow[9], 0.f);
      }
    }
    __syncthreads();

    layer64(s.w1d, s.b1, s.A, s.Bb, r0, c0);
    __syncthreads();
    layer64(s.w2d, s.b2, s.Bb, s.A, r0, c0);
    __syncthreads();

    // ---- end layer: S[8 x NCOL] = We @ X (+b_end on value cols), f32x2 col pairs ----
    // 8 rows x 144 col-pairs = 1152 slots; 384 threads -> 3 each.
    #pragma unroll
    for (int it = 0; it < 3; it++) {
      int idx = tid + it*NT;
      int r = idx / (NCOL/2), pc = idx - r*(NCOL/2);
      int c = 2*pc;
      u64 acc = 0ull;
      const float* wr = s.wed + r*2*HID;
      const float* xb = s.A + c;
      #pragma unroll 8
      for (int k = 0; k < HID; k++) {
        u64 wv = *reinterpret_cast<const u64*>(wr + 2*k);
        u64 xv = *reinterpret_cast<const u64*>(xb + k*NCOL);
        fma2(acc, wv, xv);
      }
      float lo, hi; unpack2(acc, lo, hi);
      if ((c % NC) == 0) lo += s.be[r];
      *reinterpret_cast<float2*>(s.Bb + r*NCOL + c) = make_float2(lo, hi);
    }
    __syncthreads();

    // ---- per-sample epilogue scalars ----
    if (tid < BS) {
      int sm = tid;
      int cc = sm * NC;
      float st0 = s.Bb[cc];
      float y0  = s.inp[sm][0];
      float sg  = (y0 > 0.f) ? 1.f : ((y0 < 0.f) ? -1.f : 0.f);
      float a   = fabsf(y0);
      float p   = s.pconst;
      float Ee  = s.Econst;
      float onep = 1.f + st0 * 1e-5f;
      float u   = a * onep;
      float g   = (u > 0.f) ? powf(u, p) : 0.f;   // macaulay(g)=g since g>=0
      float dgdu = (u > 0.f) ? p * g / u : 0.f;
      float coef = -Ee * sg * dgdu;
      float er  = s.inp[sm][NSIZE];
      s.sc[sm][0] = sg * onep;
      s.sc[sm][1] = a * 1e-5f;
      s.sc[sm][2] = coef;
      s.sc[sm][3] = Ee * (er - g * sg);
      s.sc[sm][4] = Ee;
    }
    __syncthreads();

    // ---- write outputs: one thread per (sample, output row) ----
    if (tid < BS*NSIZE) {
      int sm = tid >> 3;
      int r  = tid & 7;
      int g  = samp0 + sm;
      if (g < NSAMP) {
        int cc = sm * NC;
        float S[11];
        #pragma unroll
        for (int j = 0; j < 11; j++) S[j] = s.Bb[r*NCOL + cc + j];
        float son  = s.sc[sm][0], a5 = s.sc[sm][1], coef = s.sc[sm][2];
        float flow = s.sc[sm][3], Ee = s.sc[sm][4];

        float rate, j1[8], j2v, j3v;
        if (r == 0) {
          rate = flow;
          #pragma unroll
          for (int j = 0; j < 8; j++) {
            float du = a5 * S[1 + j] + (j == 0 ? son : 0.f);
            j1[j] = coef * du;
          }
          j2v = Ee + coef * (a5 * S[9]);
          j3v = coef * (a5 * S[10]);
        } else {
          rate = S[0] * 1e-4f;
          #pragma unroll
          for (int j = 0; j < 8; j++) j1[j] = S[1 + j] * 1e-4f;
          j2v = S[9]  * 1e-4f;
          j3v = S[10] * 1e-4f;
        }

        out[(size_t)g*NSIZE + r] = rate;
        const size_t b1o = (size_t)NSAMP * NSIZE;
        float* o1 = out + b1o + (size_t)g*64 + (size_t)r*8;
        #pragma unroll
        for (int j = 0; j < 8; j++) o1[j] = j1[j];
        const size_t b2o = b1o + (size_t)NSAMP * 64;
        out[b2o + (size_t)g*NSIZE + r] = j2v;
        out[b2o + (size_t)NSAMP*NSIZE + (size_t)g*NSIZE + r] = j3v;
      }
    }
    // no sync needed here: next input-load writes s.inp, which no stage after
    // the epilogue (already fenced by a sync) reads; the post-input sync fences
    // it against this tile's Bb/sc readers... (ordering argument in commit msg)
    __syncthreads();
  }
}

extern "C" void kernel_launch(void* const* d_in, const int* in_sizes, int n_in,
                              void* d_out, int out_size)
{
  const float* y       = (const float*)d_in[1];
  const float* erate   = (const float*)d_in[2];
  const float* T       = (const float*)d_in[3];
  const float* E       = (const float*)d_in[4];
  const float* n       = (const float*)d_in[5];
  const float* w_start = (const float*)d_in[6];
  const float* b_start = (const float*)d_in[7];
  const float* w_int   = (const float*)d_in[8];
  const float* b_int   = (const float*)d_in[9];
  const float* w_end   = (const float*)d_in[10];
  const float* b_end   = (const float*)d_in[11];
  float* out = (float*)d_out;

  int shbytes = (int)sizeof(SM);
  cudaFuncSetAttribute(model_kernel, cudaFuncAttributeMaxDynamicSharedMemorySize, shbytes);
  model_kernel<<<GRID, NT, shbytes>>>(y, erate, T, E, n, w_start, b_start,
                                      w_int, b_int, w_end, b_end, out);
}